// round 1
// baseline (speedup 1.0000x reference)
#include <cuda_runtime.h>
#include <math.h>

#define BATCH 4096
#define T 25
#define CT 32
#define FIN 800
#define GO 64
#define H 256
#define VE 16
#define VR 12
#define KE 400   /* VE*T */
#define KR 300   /* VR*T */
#define TB 32
#define XSE 36   /* padded smem row stride (floats), mult of 4 for f4 alignment */

// ---------------- device scratch (no allocations allowed) ----------------
__device__ float g_U[4][T * GO];   // 0:U0e 1:U1e 2:U0r 3:U1r
__device__ float g_S[4][GO];       // S0e S1e S0r S1r (conv-bias folded vectors)
__device__ float g_we[2][64];      // edge weights per graph
__device__ float g_A_ecc[KE * H];
__device__ float g_A_err[KR * H];
__device__ float g_C[2][H];

// ---------------- f32x2 helpers ----------------
__device__ __forceinline__ unsigned long long fma2(unsigned long long a,
                                                   unsigned long long b,
                                                   unsigned long long c) {
    unsigned long long d;
    asm("fma.rn.f32x2 %0, %1, %2, %3;" : "=l"(d) : "l"(a), "l"(b), "l"(c));
    return d;
}
__device__ __forceinline__ unsigned long long pack2(float x) {
    unsigned long long d;
    asm("mov.b64 %0, {%1, %1};" : "=l"(d) : "f"(x));
    return d;
}
__device__ __forceinline__ float2 unpack2(unsigned long long v) {
    float lo, hi;
    asm("mov.b64 {%0, %1}, %2;" : "=f"(lo), "=f"(hi) : "l"(v));
    return make_float2(lo, hi);
}

// ---------------- precompute: edge weights ----------------
__global__ void k_we(const int* ei_e, int Ee, const int* ei_r, int Er) {
    int g = blockIdx.x;
    const int* ei = g ? ei_r : ei_e;
    int E = g ? Er : Ee;
    int e = threadIdx.x;
    if (e < E) {
        int s = ei[e], d = ei[E + e];
        int degs = 0, degd = 0;
        for (int i = 0; i < E; i++) {
            int si = ei[i];
            degs += (si == s);
            degd += (si == d);
        }
        float dis_s = degs > 0 ? rsqrtf((float)(degs < 1 ? 1 : degs)) : 0.f;
        float dis_d = degd > 0 ? rsqrtf((float)(degd < 1 ? 1 : degd)) : 0.f;
        g_we[g][e] = -dis_s * dis_d;
    }
}

// ---------------- precompute: U matrices (conv ⊗ cheb W) and S bias vectors ----
__global__ void k_US(const float* cwe, const float* cbe,
                     const float* cwr, const float* cbr,
                     const float* Wche, const float* Wchr) {
    int idx = blockIdx.x * blockDim.x + threadIdx.x;
    if (idx < 4 * T * GO) {
        int mat = idx / (T * GO);
        int rem = idx % (T * GO);
        int tp = rem / GO, o = rem % GO;
        int branch = mat >> 1;   // 0 ecc, 1 err
        int which = mat & 1;     // cheb W[0] or W[1]
        const float* cw = branch ? cwr : cwe;
        const float* W = (branch ? Wchr : Wche) + which * FIN * GO;
        float s = 0.f;
        for (int k = 0; k < 3; k++) {
            int t = tp - k + 1;                 // input t' = t + k - 1  =>  t = t' - k + 1
            if (t >= 0 && t < T) {
                for (int c = 0; c < CT; c++)
                    s += cw[c * 3 + k] * W[(c * T + t) * GO + o];
            }
        }
        g_U[mat][rem] = s;
    } else if (idx < 4 * T * GO + 4 * GO) {
        int j = idx - 4 * T * GO;
        int mat = j / GO, o = j % GO;
        int branch = mat >> 1, which = mat & 1;
        const float* cb = branch ? cbr : cbe;
        const float* W = (branch ? Wchr : Wche) + which * FIN * GO;
        float s = 0.f;
        for (int c = 0; c < CT; c++) {
            float b = cb[c];
            for (int t = 0; t < T; t++) s += b * W[(c * T + t) * GO + o];
        }
        g_S[mat][o] = s;
    }
}

// ---------------- precompute: collapsed input->gate matrices A ----------------
__global__ void k_A(const float* Pe, const float* Pr,
                    const int* eie, int Ee, const int* eir, int Er) {
    int idx = blockIdx.x * blockDim.x + threadIdx.x;
    const float* P;
    const int* ei;
    int E;
    const float* U0;
    const float* U1;
    float* A;
    const float* we;
    if (idx < KE * H) {
        P = Pe; ei = eie; E = Ee; U0 = g_U[0]; U1 = g_U[1]; A = g_A_ecc; we = g_we[0];
    } else {
        idx -= KE * H;
        if (idx >= KR * H) return;
        P = Pr; ei = eir; E = Er; U0 = g_U[2]; U1 = g_U[3]; A = g_A_err; we = g_we[1];
    }
    int row = idx / H, h = idx % H;
    int v = row / T, tp = row % T;
    float val = 0.f;
    for (int o = 0; o < GO; o++)
        val += U0[tp * GO + o] * P[(v * GO + o) * H + h];
    for (int e = 0; e < E; e++) {
        if (ei[e] == v) {                 // edge src == v : feature of v flows to dst
            int d = ei[E + e];
            float w = we[e];
            float s = 0.f;
            for (int o = 0; o < GO; o++)
                s += U1[tp * GO + o] * P[(d * GO + o) * H + h];
            val += w * s;
        }
    }
    A[row * H + h] = val;
}

// ---------------- precompute: constant vectors C ----------------
__global__ void k_C(const float* Pe, const float* pbe, const float* chbe,
                    const float* Pr, const float* pbr, const float* chbr,
                    const int* eie, int Ee, const int* eir, int Er) {
    int branch = blockIdx.x;
    int h = threadIdx.x;
    const float* P = branch ? Pr : Pe;
    const float* pb = branch ? pbr : pbe;
    const float* chb = branch ? chbr : chbe;
    const int* ei = branch ? eir : eie;
    int E = branch ? Er : Ee;
    int V = branch ? VR : VE;
    const float* S0 = g_S[branch * 2 + 0];
    const float* S1 = g_S[branch * 2 + 1];
    const float* we = g_we[branch];
    float c = pb[h];
    for (int o = 0; o < GO; o++) {
        float ps = 0.f;
        for (int v = 0; v < V; v++) ps += P[(v * GO + o) * H + h];
        float pw = 0.f;
        for (int e = 0; e < E; e++) pw += we[e] * P[(ei[E + e] * GO + o) * H + h];
        c += (chb[o] + S0[o]) * ps + S1[o] * pw;
    }
    g_C[branch][h] = c;
}

// ---------------- main fused kernel: 2 GEMMs + gated tail ----------------
extern __shared__ float sm[];

__global__ void __launch_bounds__(256)
k_main(const float* __restrict__ ecc, const float* __restrict__ err,
       const float* __restrict__ attnW, const float* __restrict__ attnb,
       const float* __restrict__ fc2W, const float* __restrict__ fc2b,
       float* __restrict__ out) {
    float* Xe = sm;                    // [KE][XSE] transposed X_ecc tile
    float* Xr = Xe + KE * XSE;         // [KR][XSE]
    float* eg = Xr + KR * XSE;         // [TB][H]
    float* rg = eg + TB * H;           // [TB][H]

    const int tid = threadIdx.x;
    const int rb = blockIdx.x * TB;

    // stage X tiles (global coalesced on k; smem writes 4-way conflict, load-phase only)
    for (int i = tid; i < TB * KE; i += 256) {
        int r = i / KE, k = i - r * KE;
        Xe[k * XSE + r] = ecc[(rb + r) * KE + k];
    }
    for (int i = tid; i < TB * KR; i += 256) {
        int r = i / KR, k = i - r * KR;
        Xr[k * XSE + r] = err[(rb + r) * KR + k];
    }
    __syncthreads();

    const int n_id = tid & 63;   // 64 column groups of 4
    const int m_id = tid >> 6;   // 4 row groups of 8

    // -------- phase 1: ecc_g --------
    {
        unsigned long long acc[8][2];
#pragma unroll
        for (int i = 0; i < 8; i++) { acc[i][0] = 0ull; acc[i][1] = 0ull; }
        const ulonglong2* A4 = (const ulonglong2*)g_A_ecc;  // 64 ull2 per k-row
#pragma unroll 8
        for (int k = 0; k < KE; k++) {
            ulonglong2 a = A4[k * 64 + n_id];
            const float* xp = Xe + k * XSE + m_id * 8;
            float4 x0 = *(const float4*)xp;
            float4 x1 = *(const float4*)(xp + 4);
            unsigned long long xd;
            xd = pack2(x0.x); acc[0][0] = fma2(xd, a.x, acc[0][0]); acc[0][1] = fma2(xd, a.y, acc[0][1]);
            xd = pack2(x0.y); acc[1][0] = fma2(xd, a.x, acc[1][0]); acc[1][1] = fma2(xd, a.y, acc[1][1]);
            xd = pack2(x0.z); acc[2][0] = fma2(xd, a.x, acc[2][0]); acc[2][1] = fma2(xd, a.y, acc[2][1]);
            xd = pack2(x0.w); acc[3][0] = fma2(xd, a.x, acc[3][0]); acc[3][1] = fma2(xd, a.y, acc[3][1]);
            xd = pack2(x1.x); acc[4][0] = fma2(xd, a.x, acc[4][0]); acc[4][1] = fma2(xd, a.y, acc[4][1]);
            xd = pack2(x1.y); acc[5][0] = fma2(xd, a.x, acc[5][0]); acc[5][1] = fma2(xd, a.y, acc[5][1]);
            xd = pack2(x1.z); acc[6][0] = fma2(xd, a.x, acc[6][0]); acc[6][1] = fma2(xd, a.y, acc[6][1]);
            xd = pack2(x1.w); acc[7][0] = fma2(xd, a.x, acc[7][0]); acc[7][1] = fma2(xd, a.y, acc[7][1]);
        }
        float4 Cv = *(const float4*)&g_C[0][n_id * 4];
#pragma unroll
        for (int i = 0; i < 8; i++) {
            int r = m_id * 8 + i;
            float2 lo = unpack2(acc[i][0]);
            float2 hi = unpack2(acc[i][1]);
            *(float4*)&eg[r * H + n_id * 4] =
                make_float4(lo.x + Cv.x, lo.y + Cv.y, hi.x + Cv.z, hi.y + Cv.w);
        }
    }

    // -------- phase 2: err_g --------
    {
        unsigned long long acc[8][2];
#pragma unroll
        for (int i = 0; i < 8; i++) { acc[i][0] = 0ull; acc[i][1] = 0ull; }
        const ulonglong2* A4 = (const ulonglong2*)g_A_err;
#pragma unroll 8
        for (int k = 0; k < KR; k++) {
            ulonglong2 a = A4[k * 64 + n_id];
            const float* xp = Xr + k * XSE + m_id * 8;
            float4 x0 = *(const float4*)xp;
            float4 x1 = *(const float4*)(xp + 4);
            unsigned long long xd;
            xd = pack2(x0.x); acc[0][0] = fma2(xd, a.x, acc[0][0]); acc[0][1] = fma2(xd, a.y, acc[0][1]);
            xd = pack2(x0.y); acc[1][0] = fma2(xd, a.x, acc[1][0]); acc[1][1] = fma2(xd, a.y, acc[1][1]);
            xd = pack2(x0.z); acc[2][0] = fma2(xd, a.x, acc[2][0]); acc[2][1] = fma2(xd, a.y, acc[2][1]);
            xd = pack2(x0.w); acc[3][0] = fma2(xd, a.x, acc[3][0]); acc[3][1] = fma2(xd, a.y, acc[3][1]);
            xd = pack2(x1.x); acc[4][0] = fma2(xd, a.x, acc[4][0]); acc[4][1] = fma2(xd, a.y, acc[4][1]);
            xd = pack2(x1.y); acc[5][0] = fma2(xd, a.x, acc[5][0]); acc[5][1] = fma2(xd, a.y, acc[5][1]);
            xd = pack2(x1.z); acc[6][0] = fma2(xd, a.x, acc[6][0]); acc[6][1] = fma2(xd, a.y, acc[6][1]);
            xd = pack2(x1.w); acc[7][0] = fma2(xd, a.x, acc[7][0]); acc[7][1] = fma2(xd, a.y, acc[7][1]);
        }
        float4 Cv = *(const float4*)&g_C[1][n_id * 4];
#pragma unroll
        for (int i = 0; i < 8; i++) {
            int r = m_id * 8 + i;
            float2 lo = unpack2(acc[i][0]);
            float2 hi = unpack2(acc[i][1]);
            *(float4*)&rg[r * H + n_id * 4] =
                make_float4(lo.x + Cv.x, lo.y + Cv.y, hi.x + Cv.z, hi.y + Cv.w);
        }
    }
    __syncthreads();

    // -------- tail: gated fusion, 1 warp per 4 rows --------
    const int lane = tid & 31;
    const int w = tid >> 5;
    const float attnb_v = attnb[0];
    const float fc2b_v = fc2b[0];
    for (int r = w * 4; r < w * 4 + 4; r++) {
        const float* egr = eg + r * H;
        const float* rgr = rg + r * H;
        float p = 0.f;
#pragma unroll
        for (int j = lane; j < H; j += 32)
            p += tanhf(egr[j] + rgr[j]) * attnW[j];
#pragma unroll
        for (int o = 16; o; o >>= 1) p += __shfl_xor_sync(0xffffffffu, p, o);
        float attn = 1.f / (1.f + expf(-(p + attnb_v)));
        float q = 0.f;
#pragma unroll
        for (int j = lane; j < H; j += 32) {
            float f = attn * egr[j] + (1.f - attn) * rgr[j];
            q += fmaxf(f, 0.f) * fc2W[j];
        }
#pragma unroll
        for (int o = 16; o; o >>= 1) q += __shfl_xor_sync(0xffffffffu, q, o);
        if (lane == 0) out[rb + r] = 1.f / (1.f + expf(-(q + fc2b_v)));
    }
}

// ---------------- launch ----------------
extern "C" void kernel_launch(void* const* d_in, const int* in_sizes, int n_in,
                              void* d_out, int out_size) {
    const float* ecc = (const float*)d_in[0];
    const float* err = (const float*)d_in[1];
    const float* conv_ecc_w = (const float*)d_in[2];
    const float* conv_ecc_b = (const float*)d_in[3];
    const float* conv_err_w = (const float*)d_in[4];
    const float* conv_err_b = (const float*)d_in[5];
    const float* cheb_ecc_W = (const float*)d_in[6];
    const float* cheb_err_W = (const float*)d_in[8];
    const float* cheb_ecc_b = (const float*)d_in[7];
    const float* cheb_err_b = (const float*)d_in[9];
    const float* ecc_proj_W = (const float*)d_in[10];
    const float* ecc_proj_b = (const float*)d_in[11];
    const float* err_proj_W = (const float*)d_in[12];
    const float* err_proj_b = (const float*)d_in[13];
    const float* attn_W = (const float*)d_in[14];
    const float* attn_b = (const float*)d_in[15];
    const float* fc2_W = (const float*)d_in[16];
    const float* fc2_b = (const float*)d_in[17];
    const int* ei_ecc = (const int*)d_in[18];
    const int* ei_err = (const int*)d_in[19];
    const int Ee = in_sizes[18] / 2;
    const int Er = in_sizes[19] / 2;

    k_we<<<2, 64>>>(ei_ecc, Ee, ei_err, Er);
    k_US<<<26, 256>>>(conv_ecc_w, conv_ecc_b, conv_err_w, conv_err_b,
                      cheb_ecc_W, cheb_err_W);
    k_A<<<700, 256>>>(ecc_proj_W, err_proj_W, ei_ecc, Ee, ei_err, Er);
    k_C<<<2, 256>>>(ecc_proj_W, ecc_proj_b, cheb_ecc_b,
                    err_proj_W, err_proj_b, cheb_err_b,
                    ei_ecc, Ee, ei_err, Er);

    const size_t smem = (size_t)(KE * XSE + KR * XSE + 2 * TB * H) * sizeof(float);
    cudaFuncSetAttribute(k_main, cudaFuncAttributeMaxDynamicSharedMemorySize,
                         (int)smem);
    k_main<<<BATCH / TB, 256, smem>>>(ecc, err, attn_W, attn_b, fc2_W, fc2_b,
                                      (float*)d_out);
}

// round 2
// speedup vs baseline: 1.6664x; 1.6664x over previous
#include <cuda_runtime.h>
#include <math.h>

#define BATCH 4096
#define T 25
#define CT 32
#define FIN 800
#define GO 64
#define H 256
#define VE 16
#define VR 12
#define KE 400   /* VE*T */
#define KR 300   /* VR*T */
#define TB 32
#define XSE 36   /* padded smem row stride (floats), mult of 4 for f4 alignment */

// ---------------- device scratch (no allocations allowed) ----------------
__device__ float g_U[4][T * GO];   // 0:U0e 1:U1e 2:U0r 3:U1r
__device__ float g_S[4][GO];       // S0e S1e S0r S1r (conv-bias folded vectors)
__device__ float g_we[2][64];      // edge weights per graph
__device__ float g_wsum[2][16];    // sum of incoming edge weights per node
__device__ float g_A_ecc[KE * H];
__device__ float g_A_err[KR * H];
__device__ float g_C[2][H];

// ---------------- f32x2 helpers ----------------
__device__ __forceinline__ unsigned long long fma2(unsigned long long a,
                                                   unsigned long long b,
                                                   unsigned long long c) {
    unsigned long long d;
    asm("fma.rn.f32x2 %0, %1, %2, %3;" : "=l"(d) : "l"(a), "l"(b), "l"(c));
    return d;
}
__device__ __forceinline__ unsigned long long pack2(float x) {
    unsigned long long d;
    asm("mov.b64 %0, {%1, %1};" : "=l"(d) : "f"(x));
    return d;
}
__device__ __forceinline__ float2 unpack2(unsigned long long v) {
    float lo, hi;
    asm("mov.b64 {%0, %1}, %2;" : "=f"(lo), "=f"(hi) : "l"(v));
    return make_float2(lo, hi);
}

// ---------------- precompute: U, S, edge weights, wsum (one kernel) ----------
__global__ void k_prep(const float* cwe, const float* cbe,
                       const float* cwr, const float* cbr,
                       const float* Wche, const float* Wchr,
                       const int* eie, int Ee, const int* eir, int Er) {
    if (blockIdx.x < 26) {
        int idx = blockIdx.x * 256 + threadIdx.x;
        if (idx < 4 * T * GO) {
            int mat = idx / (T * GO);
            int rem = idx % (T * GO);
            int tp = rem / GO, o = rem % GO;
            int branch = mat >> 1;   // 0 ecc, 1 err
            int which = mat & 1;     // cheb W[0] or W[1]
            const float* cw = branch ? cwr : cwe;
            const float* W = (branch ? Wchr : Wche) + which * FIN * GO;
            float s = 0.f;
            for (int k = 0; k < 3; k++) {
                int t = tp - k + 1;
                if (t >= 0 && t < T) {
                    for (int c = 0; c < CT; c++)
                        s += cw[c * 3 + k] * W[(c * T + t) * GO + o];
                }
            }
            g_U[mat][rem] = s;
        } else {
            int j = idx - 4 * T * GO;   // < 4*GO = 256
            int mat = j / GO, o = j % GO;
            int branch = mat >> 1, which = mat & 1;
            const float* cb = branch ? cbr : cbe;
            const float* W = (branch ? Wchr : Wche) + which * FIN * GO;
            float s = 0.f;
            for (int c = 0; c < CT; c++) {
                float b = cb[c];
                for (int t = 0; t < T; t++) s += b * W[(c * T + t) * GO + o];
            }
            g_S[mat][o] = s;
        }
    } else {
        // edge weights + incoming-weight sums, both graphs
        int t = threadIdx.x;
        for (int g = 0; g < 2; g++) {
            const int* ei = g ? eir : eie;
            int E = g ? Er : Ee;
            int V = g ? VR : VE;
            if (t < E) {
                int s = ei[t], d = ei[E + t];
                int degs = 0, degd = 0;
                for (int i = 0; i < E; i++) {
                    int si = ei[i];
                    degs += (si == s);
                    degd += (si == d);
                }
                float ds = degs > 0 ? rsqrtf((float)degs) : 0.f;
                float dd = degd > 0 ? rsqrtf((float)degd) : 0.f;
                g_we[g][t] = -ds * dd;
            }
            __syncthreads();
            if (t < 16) {
                float s = 0.f;
                if (t < V)
                    for (int e = 0; e < E; e++)
                        if (ei[E + e] == t) s += g_we[g][e];
                g_wsum[g][t] = s;
            }
            __syncthreads();
        }
    }
}

// ---------------- precompute: A matrices (tiled) + C vectors, one kernel ------
__global__ void __launch_bounds__(256) k_AC(
    const float* __restrict__ Pe, const float* __restrict__ Pr,
    const float* __restrict__ pbe, const float* __restrict__ pbr,
    const float* __restrict__ chbe, const float* __restrict__ chbr,
    const int* __restrict__ eie, int Ee, const int* __restrict__ eir, int Er) {
    __shared__ float sP[64 * 64];
    __shared__ float sQ[64 * 64];
    __shared__ float sU0[T * GO];
    __shared__ float sU1[T * GO];
    const int tid = threadIdx.x;
    const int b = blockIdx.x;

    if (b < (VE + VR) * 4) {
        // ---- A block: node v, h-chunk hb..hb+63 ----
        const int vb = b >> 2, hb = (b & 3) * 64;
        const int br = vb >= VE;
        const int v = br ? vb - VE : vb;
        const float* P = br ? Pr : Pe;
        const int* ei = br ? eir : eie;
        const int E = br ? Er : Ee;
        const float* U0 = g_U[2 * br];
        const float* U1 = g_U[2 * br + 1];
        float* A = br ? g_A_err : g_A_ecc;

        for (int i = tid; i < T * GO; i += 256) {
            sU0[i] = U0[i];
            sU1[i] = U1[i];
        }
        for (int i = tid; i < 4096; i += 256) {
            int o = i >> 6, hl = i & 63;
            sP[i] = P[(v * GO + o) * H + hb + hl];
            sQ[i] = 0.f;
        }
        __syncthreads();
        for (int e = 0; e < E; e++) {
            if (ei[e] == v) {
                int d = ei[E + e];
                float w = g_we[br][e];
                for (int i = tid; i < 4096; i += 256) {
                    int o = i >> 6, hl = i & 63;
                    sQ[i] += w * P[(d * GO + o) * H + hb + hl];
                }
            }
        }
        __syncthreads();

        const int hl4 = (tid & 15) * 4;
        const int tpg = tid >> 4;
        for (int tp = tpg; tp < T; tp += 16) {
            float4 acc = make_float4(0.f, 0.f, 0.f, 0.f);
#pragma unroll 16
            for (int o = 0; o < 64; o++) {
                float4 p = *(const float4*)&sP[o * 64 + hl4];
                float4 q = *(const float4*)&sQ[o * 64 + hl4];
                float u0 = sU0[tp * GO + o];
                float u1 = sU1[tp * GO + o];
                acc.x += u0 * p.x + u1 * q.x;
                acc.y += u0 * p.y + u1 * q.y;
                acc.z += u0 * p.z + u1 * q.z;
                acc.w += u0 * p.w + u1 * q.w;
            }
            *(float4*)&A[(v * T + tp) * H + hb + hl4] = acc;
        }
    } else {
        // ---- C block: branch br, 32 h-columns ----
        const int cb = b - (VE + VR) * 4;   // 0..15
        const int br = cb >> 3;
        const int hc = cb & 7;
        const float* chb = br ? chbr : chbe;
        const float* pb = br ? pbr : pbe;
        const float* P = br ? Pr : Pe;
        const int V = br ? VR : VE;
        float* cfo = sP;          // 64: chb + S0
        float* s1v = sP + 64;     // 64: S1
        float* ws = sP + 128;     // 16: wsum
        float* red = sP + 160;    // 256: partials

        if (tid < 64) {
            cfo[tid] = chb[tid] + g_S[2 * br][tid];
            s1v[tid] = g_S[2 * br + 1][tid];
        }
        if (tid < 16) ws[tid] = g_wsum[br][tid];
        __syncthreads();

        const int lane = tid & 31, rp = tid >> 5;
        const int h = hc * 32 + lane;
        const int R = V * GO;
        const int RP = R >> 3;
        float acc = 0.f;
#pragma unroll 4
        for (int r = rp * RP; r < (rp + 1) * RP; r++) {
            int o = r & 63, v = r >> 6;
            float coef = cfo[o] + s1v[o] * ws[v];
            acc += coef * P[r * H + h];
        }
        red[tid] = acc;
        __syncthreads();
        if (tid < 32) {
            float s = pb[h];
#pragma unroll
            for (int j = 0; j < 8; j++) s += red[j * 32 + lane];
            g_C[br][h] = s;
        }
    }
}

// ---------------- main fused kernel: 2 GEMMs + gated tail ----------------
extern __shared__ float sm[];

__global__ void __launch_bounds__(256)
k_main(const float* __restrict__ ecc, const float* __restrict__ err,
       const float* __restrict__ attnW, const float* __restrict__ attnb,
       const float* __restrict__ fc2W, const float* __restrict__ fc2b,
       float* __restrict__ out) {
    float* Xe = sm;                    // [KE][XSE] transposed X_ecc tile
    float* Xr = Xe + KE * XSE;         // [KR][XSE]
    float* eg = Xr + KR * XSE;         // [TB][H]
    float* rg = eg + TB * H;           // [TB][H]

    const int tid = threadIdx.x;
    const int rb = blockIdx.x * TB;

    for (int i = tid; i < TB * KE; i += 256) {
        int r = i / KE, k = i - r * KE;
        Xe[k * XSE + r] = ecc[(rb + r) * KE + k];
    }
    for (int i = tid; i < TB * KR; i += 256) {
        int r = i / KR, k = i - r * KR;
        Xr[k * XSE + r] = err[(rb + r) * KR + k];
    }
    __syncthreads();

    const int n_id = tid & 63;   // 64 column groups of 4
    const int m_id = tid >> 6;   // 4 row groups of 8

    // -------- phase 1: ecc_g --------
    {
        unsigned long long acc[8][2];
#pragma unroll
        for (int i = 0; i < 8; i++) { acc[i][0] = 0ull; acc[i][1] = 0ull; }
        const ulonglong2* A4 = (const ulonglong2*)g_A_ecc;
#pragma unroll 8
        for (int k = 0; k < KE; k++) {
            ulonglong2 a = A4[k * 64 + n_id];
            const float* xp = Xe + k * XSE + m_id * 8;
            float4 x0 = *(const float4*)xp;
            float4 x1 = *(const float4*)(xp + 4);
            unsigned long long xd;
            xd = pack2(x0.x); acc[0][0] = fma2(xd, a.x, acc[0][0]); acc[0][1] = fma2(xd, a.y, acc[0][1]);
            xd = pack2(x0.y); acc[1][0] = fma2(xd, a.x, acc[1][0]); acc[1][1] = fma2(xd, a.y, acc[1][1]);
            xd = pack2(x0.z); acc[2][0] = fma2(xd, a.x, acc[2][0]); acc[2][1] = fma2(xd, a.y, acc[2][1]);
            xd = pack2(x0.w); acc[3][0] = fma2(xd, a.x, acc[3][0]); acc[3][1] = fma2(xd, a.y, acc[3][1]);
            xd = pack2(x1.x); acc[4][0] = fma2(xd, a.x, acc[4][0]); acc[4][1] = fma2(xd, a.y, acc[4][1]);
            xd = pack2(x1.y); acc[5][0] = fma2(xd, a.x, acc[5][0]); acc[5][1] = fma2(xd, a.y, acc[5][1]);
            xd = pack2(x1.z); acc[6][0] = fma2(xd, a.x, acc[6][0]); acc[6][1] = fma2(xd, a.y, acc[6][1]);
            xd = pack2(x1.w); acc[7][0] = fma2(xd, a.x, acc[7][0]); acc[7][1] = fma2(xd, a.y, acc[7][1]);
        }
        float4 Cv = *(const float4*)&g_C[0][n_id * 4];
#pragma unroll
        for (int i = 0; i < 8; i++) {
            int r = m_id * 8 + i;
            float2 lo = unpack2(acc[i][0]);
            float2 hi = unpack2(acc[i][1]);
            *(float4*)&eg[r * H + n_id * 4] =
                make_float4(lo.x + Cv.x, lo.y + Cv.y, hi.x + Cv.z, hi.y + Cv.w);
        }
    }

    // -------- phase 2: err_g --------
    {
        unsigned long long acc[8][2];
#pragma unroll
        for (int i = 0; i < 8; i++) { acc[i][0] = 0ull; acc[i][1] = 0ull; }
        const ulonglong2* A4 = (const ulonglong2*)g_A_err;
#pragma unroll 8
        for (int k = 0; k < KR; k++) {
            ulonglong2 a = A4[k * 64 + n_id];
            const float* xp = Xr + k * XSE + m_id * 8;
            float4 x0 = *(const float4*)xp;
            float4 x1 = *(const float4*)(xp + 4);
            unsigned long long xd;
            xd = pack2(x0.x); acc[0][0] = fma2(xd, a.x, acc[0][0]); acc[0][1] = fma2(xd, a.y, acc[0][1]);
            xd = pack2(x0.y); acc[1][0] = fma2(xd, a.x, acc[1][0]); acc[1][1] = fma2(xd, a.y, acc[1][1]);
            xd = pack2(x0.z); acc[2][0] = fma2(xd, a.x, acc[2][0]); acc[2][1] = fma2(xd, a.y, acc[2][1]);
            xd = pack2(x0.w); acc[3][0] = fma2(xd, a.x, acc[3][0]); acc[3][1] = fma2(xd, a.y, acc[3][1]);
            xd = pack2(x1.x); acc[4][0] = fma2(xd, a.x, acc[4][0]); acc[4][1] = fma2(xd, a.y, acc[4][1]);
            xd = pack2(x1.y); acc[5][0] = fma2(xd, a.x, acc[5][0]); acc[5][1] = fma2(xd, a.y, acc[5][1]);
            xd = pack2(x1.z); acc[6][0] = fma2(xd, a.x, acc[6][0]); acc[6][1] = fma2(xd, a.y, acc[6][1]);
            xd = pack2(x1.w); acc[7][0] = fma2(xd, a.x, acc[7][0]); acc[7][1] = fma2(xd, a.y, acc[7][1]);
        }
        float4 Cv = *(const float4*)&g_C[1][n_id * 4];
#pragma unroll
        for (int i = 0; i < 8; i++) {
            int r = m_id * 8 + i;
            float2 lo = unpack2(acc[i][0]);
            float2 hi = unpack2(acc[i][1]);
            *(float4*)&rg[r * H + n_id * 4] =
                make_float4(lo.x + Cv.x, lo.y + Cv.y, hi.x + Cv.z, hi.y + Cv.w);
        }
    }
    __syncthreads();

    // -------- tail: gated fusion, 1 warp per 4 rows --------
    const int lane = tid & 31;
    const int w = tid >> 5;
    const float attnb_v = attnb[0];
    const float fc2b_v = fc2b[0];
    for (int r = w * 4; r < w * 4 + 4; r++) {
        const float* egr = eg + r * H;
        const float* rgr = rg + r * H;
        float p = 0.f;
#pragma unroll
        for (int j = lane; j < H; j += 32)
            p += tanhf(egr[j] + rgr[j]) * attnW[j];
#pragma unroll
        for (int o = 16; o; o >>= 1) p += __shfl_xor_sync(0xffffffffu, p, o);
        float attn = 1.f / (1.f + expf(-(p + attnb_v)));
        float q = 0.f;
#pragma unroll
        for (int j = lane; j < H; j += 32) {
            float f = attn * egr[j] + (1.f - attn) * rgr[j];
            q += fmaxf(f, 0.f) * fc2W[j];
        }
#pragma unroll
        for (int o = 16; o; o >>= 1) q += __shfl_xor_sync(0xffffffffu, q, o);
        if (lane == 0) out[rb + r] = 1.f / (1.f + expf(-(q + fc2b_v)));
    }
}

// ---------------- launch ----------------
extern "C" void kernel_launch(void* const* d_in, const int* in_sizes, int n_in,
                              void* d_out, int out_size) {
    const float* ecc = (const float*)d_in[0];
    const float* err = (const float*)d_in[1];
    const float* conv_ecc_w = (const float*)d_in[2];
    const float* conv_ecc_b = (const float*)d_in[3];
    const float* conv_err_w = (const float*)d_in[4];
    const float* conv_err_b = (const float*)d_in[5];
    const float* cheb_ecc_W = (const float*)d_in[6];
    const float* cheb_ecc_b = (const float*)d_in[7];
    const float* cheb_err_W = (const float*)d_in[8];
    const float* cheb_err_b = (const float*)d_in[9];
    const float* ecc_proj_W = (const float*)d_in[10];
    const float* ecc_proj_b = (const float*)d_in[11];
    const float* err_proj_W = (const float*)d_in[12];
    const float* err_proj_b = (const float*)d_in[13];
    const float* attn_W = (const float*)d_in[14];
    const float* attn_b = (const float*)d_in[15];
    const float* fc2_W = (const float*)d_in[16];
    const float* fc2_b = (const float*)d_in[17];
    const int* ei_ecc = (const int*)d_in[18];
    const int* ei_err = (const int*)d_in[19];
    const int Ee = in_sizes[18] / 2;
    const int Er = in_sizes[19] / 2;

    k_prep<<<27, 256>>>(conv_ecc_w, conv_ecc_b, conv_err_w, conv_err_b,
                        cheb_ecc_W, cheb_err_W, ei_ecc, Ee, ei_err, Er);
    k_AC<<<(VE + VR) * 4 + 16, 256>>>(ecc_proj_W, err_proj_W,
                                      ecc_proj_b, err_proj_b,
                                      cheb_ecc_b, cheb_err_b,
                                      ei_ecc, Ee, ei_err, Er);

    const size_t smem = (size_t)(KE * XSE + KR * XSE + 2 * TB * H) * sizeof(float);
    cudaFuncSetAttribute(k_main, cudaFuncAttributeMaxDynamicSharedMemorySize,
                         (int)smem);
    k_main<<<BATCH / TB, 256, smem>>>(ecc, err, attn_W, attn_b, fc2_W, fc2_b,
                                      (float*)d_out);
}

// round 3
// speedup vs baseline: 1.9740x; 1.1846x over previous
#include <cuda_runtime.h>
#include <math.h>

#define BATCH 4096
#define T 25
#define CT 32
#define FIN 800
#define GO 64
#define H 256
#define VE 16
#define VR 12
#define KE 400   /* VE*T */
#define KR 300   /* VR*T */
#define TB 32
#define XSE 36   /* padded smem row stride (floats), mult of 4 for f4 alignment */

// ---------------- device scratch (no allocations allowed) ----------------
__device__ float g_U[4][T * GO];   // 0:U0e 1:U1e 2:U0r 3:U1r
__device__ float g_S[4][GO];       // S0e S1e S0r S1r (conv-bias folded vectors)
__device__ float g_we[2][64];      // edge weights per graph
__device__ float g_wsum[2][16];    // sum of incoming edge weights per node
__device__ int   g_nbrd[2][16][8]; // per-src-node neighbor dst list
__device__ float g_nbrw[2][16][8]; // per-src-node edge weights
__device__ int   g_ncnt[2][16];
__device__ float g_A_ecc[KE * H];
__device__ float g_A_err[KR * H];
__device__ float g_C[2][H];

// ---------------- f32x2 helpers ----------------
__device__ __forceinline__ unsigned long long fma2(unsigned long long a,
                                                   unsigned long long b,
                                                   unsigned long long c) {
    unsigned long long d;
    asm("fma.rn.f32x2 %0, %1, %2, %3;" : "=l"(d) : "l"(a), "l"(b), "l"(c));
    return d;
}
__device__ __forceinline__ unsigned long long pack2(float x) {
    unsigned long long d;
    asm("mov.b64 %0, {%1, %1};" : "=l"(d) : "f"(x));
    return d;
}
__device__ __forceinline__ float2 unpack2(unsigned long long v) {
    float lo, hi;
    asm("mov.b64 {%0, %1}, %2;" : "=f"(lo), "=f"(hi) : "l"(v));
    return make_float2(lo, hi);
}

// ---------------- precompute: U, S, edges, nbr lists (105 blocks) ------------
__global__ void __launch_bounds__(256) k_prep(
    const float* __restrict__ cwe, const float* __restrict__ cbe,
    const float* __restrict__ cwr, const float* __restrict__ cbr,
    const float* __restrict__ Wche, const float* __restrict__ Wchr,
    const int* __restrict__ eie, int Ee, const int* __restrict__ eir, int Er) {
    __shared__ float red[256];
    const int b = blockIdx.x;
    const int tid = threadIdx.x;
    const int o = tid & 63;
    const int cc = tid >> 6;   // 0..3, c-chunk

    if (b < 4 * T) {
        // ---- U: one (mat, tp) row per block, 4-way c-split ----
        const int mat = b / T, tp = b % T;
        const int branch = mat >> 1, which = mat & 1;
        const float* cw = branch ? cwr : cwe;
        const float* W = (branch ? Wchr : Wche) + which * FIN * GO;
        float acc = 0.f;
#pragma unroll
        for (int k = 0; k < 3; k++) {
            int t = tp - k + 1;
            if (t >= 0 && t < T) {
#pragma unroll
                for (int cj = 0; cj < 8; cj++) {
                    int c = cc * 8 + cj;
                    acc += cw[c * 3 + k] * W[(c * T + t) * GO + o];
                }
            }
        }
        red[tid] = acc;
        __syncthreads();
        if (tid < 64)
            g_U[mat][tp * GO + tid] =
                red[tid] + red[64 + tid] + red[128 + tid] + red[192 + tid];
    } else if (b < 4 * T + 4) {
        // ---- S bias vectors: one mat per block, 4-way c-split ----
        const int mat = b - 4 * T;
        const int branch = mat >> 1, which = mat & 1;
        const float* cb = branch ? cbr : cbe;
        const float* W = (branch ? Wchr : Wche) + which * FIN * GO;
        float acc = 0.f;
#pragma unroll
        for (int cj = 0; cj < 8; cj++) {
            int c = cc * 8 + cj;
            float s = 0.f;
#pragma unroll
            for (int t = 0; t < T; t++) s += W[(c * T + t) * GO + o];
            acc += cb[c] * s;
        }
        red[tid] = acc;
        __syncthreads();
        if (tid < 64)
            g_S[mat][tid] =
                red[tid] + red[64 + tid] + red[128 + tid] + red[192 + tid];
    } else {
        // ---- edges: weights, wsum, neighbor lists ----
        int t = tid;
        for (int g = 0; g < 2; g++) {
            const int* ei = g ? eir : eie;
            int E = g ? Er : Ee;
            int V = g ? VR : VE;
            if (t < E) {
                int s = ei[t], d = ei[E + t];
                int degs = 0, degd = 0;
                for (int i = 0; i < E; i++) {
                    int si = ei[i];
                    degs += (si == s);
                    degd += (si == d);
                }
                float ds = degs > 0 ? rsqrtf((float)degs) : 0.f;
                float dd = degd > 0 ? rsqrtf((float)degd) : 0.f;
                g_we[g][t] = -ds * dd;
            }
            __syncthreads();
            if (t < 16) {
                float ws = 0.f;
                int cnt = 0;
                if (t < V) {
                    for (int e = 0; e < E; e++) {
                        if (ei[E + e] == t) ws += g_we[g][e];
                        if (ei[e] == t && cnt < 8) {
                            g_nbrd[g][t][cnt] = ei[E + e];
                            g_nbrw[g][t][cnt] = g_we[g][e];
                            cnt++;
                        }
                    }
                }
                g_wsum[g][t] = ws;
                g_ncnt[g][t] = cnt;
            }
            __syncthreads();
        }
    }
}

// ---------------- precompute: A matrices (tiled) + C vectors, one kernel ------
__global__ void __launch_bounds__(256) k_AC(
    const float* __restrict__ Pe, const float* __restrict__ Pr,
    const float* __restrict__ pbe, const float* __restrict__ pbr,
    const float* __restrict__ chbe, const float* __restrict__ chbr) {
    __shared__ float sP[64 * 64];
    __shared__ float sQ[64 * 64];
    __shared__ float sU0[T * GO];
    __shared__ float sU1[T * GO];
    const int tid = threadIdx.x;
    const int b = blockIdx.x;

    if (b < (VE + VR) * 4) {
        // ---- A block: node v, h-chunk hb..hb+63 ----
        const int vb = b >> 2, hb = (b & 3) * 64;
        const int br = vb >= VE;
        const int v = br ? vb - VE : vb;
        const float* P = br ? Pr : Pe;
        float* A = br ? g_A_err : g_A_ecc;

        {
            const float4* U0 = (const float4*)g_U[2 * br];
            const float4* U1 = (const float4*)g_U[2 * br + 1];
            float4* s0 = (float4*)sU0;
            float4* s1 = (float4*)sU1;
            for (int i = tid; i < T * GO / 4; i += 256) {
                s0[i] = U0[i];
                s1[i] = U1[i];
            }
        }
        const int cnt = g_ncnt[br][v];
        int nd[4];
        float nw[4];
#pragma unroll
        for (int j = 0; j < 4; j++) {
            nd[j] = (j < cnt) ? g_nbrd[br][v][j] : 0;
            nw[j] = (j < cnt) ? g_nbrw[br][v][j] : 0.f;
        }
        // stage sP and sQ with float4 (1024 vec elements, 4 iters)
        for (int i4 = tid; i4 < 1024; i4 += 256) {
            int oo = i4 >> 4, hl4 = (i4 & 15) * 4;
            const float4* pv =
                (const float4*)&P[(v * GO + oo) * H + hb + hl4];
            ((float4*)sP)[i4] = *pv;
            float4 q = make_float4(0.f, 0.f, 0.f, 0.f);
#pragma unroll
            for (int j = 0; j < 4; j++) {
                if (j < cnt) {
                    float4 pd = *(const float4*)&P[(nd[j] * GO + oo) * H + hb + hl4];
                    q.x += nw[j] * pd.x;
                    q.y += nw[j] * pd.y;
                    q.z += nw[j] * pd.z;
                    q.w += nw[j] * pd.w;
                }
            }
            ((float4*)sQ)[i4] = q;
        }
        __syncthreads();

        const int hl4 = (tid & 15) * 4;
        const int tpg = tid >> 4;
        for (int tp = tpg; tp < T; tp += 16) {
            float4 acc = make_float4(0.f, 0.f, 0.f, 0.f);
#pragma unroll 16
            for (int o = 0; o < 64; o++) {
                float4 p = *(const float4*)&sP[o * 64 + hl4];
                float4 q = *(const float4*)&sQ[o * 64 + hl4];
                float u0 = sU0[tp * GO + o];
                float u1 = sU1[tp * GO + o];
                acc.x += u0 * p.x + u1 * q.x;
                acc.y += u0 * p.y + u1 * q.y;
                acc.z += u0 * p.z + u1 * q.z;
                acc.w += u0 * p.w + u1 * q.w;
            }
            *(float4*)&A[(v * T + tp) * H + hb + hl4] = acc;
        }
    } else {
        // ---- C block: branch br, 32 h-columns ----
        const int cb = b - (VE + VR) * 4;   // 0..15
        const int br = cb >> 3;
        const int hc = cb & 7;
        const float* chb = br ? chbr : chbe;
        const float* pb = br ? pbr : pbe;
        const float* P = br ? Pr : Pe;
        const int V = br ? VR : VE;
        float* cfo = sP;          // 64: chb + S0
        float* s1v = sP + 64;     // 64: S1
        float* ws = sP + 128;     // 16: wsum
        float* red = sP + 160;    // 256: partials

        if (tid < 64) {
            cfo[tid] = chb[tid] + g_S[2 * br][tid];
            s1v[tid] = g_S[2 * br + 1][tid];
        }
        if (tid < 16) ws[tid] = g_wsum[br][tid];
        __syncthreads();

        const int lane = tid & 31, rp = tid >> 5;
        const int h = hc * 32 + lane;
        const int R = V * GO;
        const int RP = R >> 3;
        float acc = 0.f;
#pragma unroll 4
        for (int r = rp * RP; r < (rp + 1) * RP; r++) {
            int o = r & 63, v = r >> 6;
            float coef = cfo[o] + s1v[o] * ws[v];
            acc += coef * P[r * H + h];
        }
        red[tid] = acc;
        __syncthreads();
        if (tid < 32) {
            float s = pb[h];
#pragma unroll
            for (int j = 0; j < 8; j++) s += red[j * 32 + lane];
            g_C[br][h] = s;
        }
    }
}

// ---------------- main fused kernel: 2 GEMMs + gated tail ----------------
extern __shared__ float sm[];

__global__ void __launch_bounds__(256)
k_main(const float* __restrict__ ecc, const float* __restrict__ err,
       const float* __restrict__ attnW, const float* __restrict__ attnb,
       const float* __restrict__ fc2W, const float* __restrict__ fc2b,
       float* __restrict__ out) {
    float* Xe = sm;                    // [KE][XSE] transposed X_ecc tile
    float* Xr = Xe + KE * XSE;         // [KR][XSE]
    float* eg = Xr + KR * XSE;         // [TB][H]
    float* rg = eg + TB * H;           // [TB][H]

    const int tid = threadIdx.x;
    const int rb = blockIdx.x * TB;

    for (int i = tid; i < TB * KE; i += 256) {
        int r = i / KE, k = i - r * KE;
        Xe[k * XSE + r] = ecc[(rb + r) * KE + k];
    }
    for (int i = tid; i < TB * KR; i += 256) {
        int r = i / KR, k = i - r * KR;
        Xr[k * XSE + r] = err[(rb + r) * KR + k];
    }
    __syncthreads();

    const int n_id = tid & 63;   // 64 column groups of 4
    const int m_id = tid >> 6;   // 4 row groups of 8

    // -------- phase 1: ecc_g --------
    {
        unsigned long long acc[8][2];
#pragma unroll
        for (int i = 0; i < 8; i++) { acc[i][0] = 0ull; acc[i][1] = 0ull; }
        const ulonglong2* A4 = (const ulonglong2*)g_A_ecc;
#pragma unroll 8
        for (int k = 0; k < KE; k++) {
            ulonglong2 a = A4[k * 64 + n_id];
            const float* xp = Xe + k * XSE + m_id * 8;
            float4 x0 = *(const float4*)xp;
            float4 x1 = *(const float4*)(xp + 4);
            unsigned long long xd;
            xd = pack2(x0.x); acc[0][0] = fma2(xd, a.x, acc[0][0]); acc[0][1] = fma2(xd, a.y, acc[0][1]);
            xd = pack2(x0.y); acc[1][0] = fma2(xd, a.x, acc[1][0]); acc[1][1] = fma2(xd, a.y, acc[1][1]);
            xd = pack2(x0.z); acc[2][0] = fma2(xd, a.x, acc[2][0]); acc[2][1] = fma2(xd, a.y, acc[2][1]);
            xd = pack2(x0.w); acc[3][0] = fma2(xd, a.x, acc[3][0]); acc[3][1] = fma2(xd, a.y, acc[3][1]);
            xd = pack2(x1.x); acc[4][0] = fma2(xd, a.x, acc[4][0]); acc[4][1] = fma2(xd, a.y, acc[4][1]);
            xd = pack2(x1.y); acc[5][0] = fma2(xd, a.x, acc[5][0]); acc[5][1] = fma2(xd, a.y, acc[5][1]);
            xd = pack2(x1.z); acc[6][0] = fma2(xd, a.x, acc[6][0]); acc[6][1] = fma2(xd, a.y, acc[6][1]);
            xd = pack2(x1.w); acc[7][0] = fma2(xd, a.x, acc[7][0]); acc[7][1] = fma2(xd, a.y, acc[7][1]);
        }
        float4 Cv = *(const float4*)&g_C[0][n_id * 4];
#pragma unroll
        for (int i = 0; i < 8; i++) {
            int r = m_id * 8 + i;
            float2 lo = unpack2(acc[i][0]);
            float2 hi = unpack2(acc[i][1]);
            *(float4*)&eg[r * H + n_id * 4] =
                make_float4(lo.x + Cv.x, lo.y + Cv.y, hi.x + Cv.z, hi.y + Cv.w);
        }
    }

    // -------- phase 2: err_g --------
    {
        unsigned long long acc[8][2];
#pragma unroll
        for (int i = 0; i < 8; i++) { acc[i][0] = 0ull; acc[i][1] = 0ull; }
        const ulonglong2* A4 = (const ulonglong2*)g_A_err;
#pragma unroll 8
        for (int k = 0; k < KR; k++) {
            ulonglong2 a = A4[k * 64 + n_id];
            const float* xp = Xr + k * XSE + m_id * 8;
            float4 x0 = *(const float4*)xp;
            float4 x1 = *(const float4*)(xp + 4);
            unsigned long long xd;
            xd = pack2(x0.x); acc[0][0] = fma2(xd, a.x, acc[0][0]); acc[0][1] = fma2(xd, a.y, acc[0][1]);
            xd = pack2(x0.y); acc[1][0] = fma2(xd, a.x, acc[1][0]); acc[1][1] = fma2(xd, a.y, acc[1][1]);
            xd = pack2(x0.z); acc[2][0] = fma2(xd, a.x, acc[2][0]); acc[2][1] = fma2(xd, a.y, acc[2][1]);
            xd = pack2(x0.w); acc[3][0] = fma2(xd, a.x, acc[3][0]); acc[3][1] = fma2(xd, a.y, acc[3][1]);
            xd = pack2(x1.x); acc[4][0] = fma2(xd, a.x, acc[4][0]); acc[4][1] = fma2(xd, a.y, acc[4][1]);
            xd = pack2(x1.y); acc[5][0] = fma2(xd, a.x, acc[5][0]); acc[5][1] = fma2(xd, a.y, acc[5][1]);
            xd = pack2(x1.z); acc[6][0] = fma2(xd, a.x, acc[6][0]); acc[6][1] = fma2(xd, a.y, acc[6][1]);
            xd = pack2(x1.w); acc[7][0] = fma2(xd, a.x, acc[7][0]); acc[7][1] = fma2(xd, a.y, acc[7][1]);
        }
        float4 Cv = *(const float4*)&g_C[1][n_id * 4];
#pragma unroll
        for (int i = 0; i < 8; i++) {
            int r = m_id * 8 + i;
            float2 lo = unpack2(acc[i][0]);
            float2 hi = unpack2(acc[i][1]);
            *(float4*)&rg[r * H + n_id * 4] =
                make_float4(lo.x + Cv.x, lo.y + Cv.y, hi.x + Cv.z, hi.y + Cv.w);
        }
    }
    __syncthreads();

    // -------- tail: gated fusion, 1 warp per 4 rows --------
    const int lane = tid & 31;
    const int w = tid >> 5;
    const float attnb_v = attnb[0];
    const float fc2b_v = fc2b[0];
    for (int r = w * 4; r < w * 4 + 4; r++) {
        const float* egr = eg + r * H;
        const float* rgr = rg + r * H;
        float p = 0.f;
#pragma unroll
        for (int j = lane; j < H; j += 32)
            p += tanhf(egr[j] + rgr[j]) * attnW[j];
#pragma unroll
        for (int o = 16; o; o >>= 1) p += __shfl_xor_sync(0xffffffffu, p, o);
        float attn = 1.f / (1.f + expf(-(p + attnb_v)));
        float q = 0.f;
#pragma unroll
        for (int j = lane; j < H; j += 32) {
            float f = attn * egr[j] + (1.f - attn) * rgr[j];
            q += fmaxf(f, 0.f) * fc2W[j];
        }
#pragma unroll
        for (int o = 16; o; o >>= 1) q += __shfl_xor_sync(0xffffffffu, q, o);
        if (lane == 0) out[rb + r] = 1.f / (1.f + expf(-(q + fc2b_v)));
    }
}

// ---------------- launch ----------------
extern "C" void kernel_launch(void* const* d_in, const int* in_sizes, int n_in,
                              void* d_out, int out_size) {
    const float* ecc = (const float*)d_in[0];
    const float* err = (const float*)d_in[1];
    const float* conv_ecc_w = (const float*)d_in[2];
    const float* conv_ecc_b = (const float*)d_in[3];
    const float* conv_err_w = (const float*)d_in[4];
    const float* conv_err_b = (const float*)d_in[5];
    const float* cheb_ecc_W = (const float*)d_in[6];
    const float* cheb_ecc_b = (const float*)d_in[7];
    const float* cheb_err_W = (const float*)d_in[8];
    const float* cheb_err_b = (const float*)d_in[9];
    const float* ecc_proj_W = (const float*)d_in[10];
    const float* ecc_proj_b = (const float*)d_in[11];
    const float* err_proj_W = (const float*)d_in[12];
    const float* err_proj_b = (const float*)d_in[13];
    const float* attn_W = (const float*)d_in[14];
    const float* attn_b = (const float*)d_in[15];
    const float* fc2_W = (const float*)d_in[16];
    const float* fc2_b = (const float*)d_in[17];
    const int* ei_ecc = (const int*)d_in[18];
    const int* ei_err = (const int*)d_in[19];
    const int Ee = in_sizes[18] / 2;
    const int Er = in_sizes[19] / 2;

    k_prep<<<4 * T + 5, 256>>>(conv_ecc_w, conv_ecc_b, conv_err_w, conv_err_b,
                               cheb_ecc_W, cheb_err_W, ei_ecc, Ee, ei_err, Er);
    k_AC<<<(VE + VR) * 4 + 16, 256>>>(ecc_proj_W, err_proj_W,
                                      ecc_proj_b, err_proj_b,
                                      cheb_ecc_b, cheb_err_b);

    const size_t smem = (size_t)(KE * XSE + KR * XSE + 2 * TB * H) * sizeof(float);
    cudaFuncSetAttribute(k_main, cudaFuncAttributeMaxDynamicSharedMemorySize,
                         (int)smem);
    k_main<<<BATCH / TB, 256, smem>>>(ecc, err, attn_W, attn_b, fc2_W, fc2_b,
                                      (float*)d_out);
}

// round 4
// speedup vs baseline: 2.1219x; 1.0750x over previous
#include <cuda_runtime.h>
#include <math.h>

#define BATCH 4096
#define T 25
#define CT 32
#define FIN 800
#define GO 64
#define H 256
#define VE 16
#define VR 12
#define KE 400   /* VE*T */
#define KR 300   /* VR*T */
#define TB 32
#define XSE 36   /* padded smem row stride (floats), mult of 4 for f4 alignment */
#define PFD 4    /* A-operand prefetch depth */

// ---------------- device scratch (no allocations allowed) ----------------
__device__ float g_U[4][T * GO];   // 0:U0e 1:U1e 2:U0r 3:U1r
__device__ float g_S[4][GO];       // S0e S1e S0r S1r (conv-bias folded vectors)
__device__ float g_we[2][64];      // edge weights per graph
__device__ float g_wsum[2][16];    // sum of incoming edge weights per node
__device__ int   g_nbrd[2][16][8]; // per-src-node neighbor dst list
__device__ float g_nbrw[2][16][8]; // per-src-node edge weights
__device__ int   g_ncnt[2][16];
__device__ float g_A_ecc[(KE + PFD) * H];   // padded for prefetch over-read
__device__ float g_A_err[(KR + PFD) * H];
__device__ float g_C[2][H];

// ---------------- f32x2 helpers ----------------
__device__ __forceinline__ unsigned long long fma2(unsigned long long a,
                                                   unsigned long long b,
                                                   unsigned long long c) {
    unsigned long long d;
    asm("fma.rn.f32x2 %0, %1, %2, %3;" : "=l"(d) : "l"(a), "l"(b), "l"(c));
    return d;
}
__device__ __forceinline__ unsigned long long pack2(float x) {
    unsigned long long d;
    asm("mov.b64 %0, {%1, %1};" : "=l"(d) : "f"(x));
    return d;
}
__device__ __forceinline__ float2 unpack2(unsigned long long v) {
    float lo, hi;
    asm("mov.b64 {%0, %1}, %2;" : "=f"(lo), "=f"(hi) : "l"(v));
    return make_float2(lo, hi);
}

// ---------------- precompute: U, S, edges, nbr lists ------------
__global__ void __launch_bounds__(256) k_prep(
    const float* __restrict__ cwe, const float* __restrict__ cbe,
    const float* __restrict__ cwr, const float* __restrict__ cbr,
    const float* __restrict__ Wche, const float* __restrict__ Wchr,
    const int* __restrict__ eie, int Ee, const int* __restrict__ eir, int Er) {
    __shared__ float red[256];
    const int b = blockIdx.x;
    const int tid = threadIdx.x;
    const int o = tid & 63;
    const int cc = tid >> 6;   // 0..3, c-chunk

    if (b < 4 * T) {
        // ---- U: one (mat, tp) row per block, 4-way c-split ----
        const int mat = b / T, tp = b % T;
        const int branch = mat >> 1, which = mat & 1;
        const float* cw = branch ? cwr : cwe;
        const float* W = (branch ? Wchr : Wche) + which * FIN * GO;
        float acc = 0.f;
#pragma unroll
        for (int k = 0; k < 3; k++) {
            int t = tp - k + 1;
            if (t >= 0 && t < T) {
#pragma unroll
                for (int cj = 0; cj < 8; cj++) {
                    int c = cc * 8 + cj;
                    acc += cw[c * 3 + k] * W[(c * T + t) * GO + o];
                }
            }
        }
        red[tid] = acc;
        __syncthreads();
        if (tid < 64)
            g_U[mat][tp * GO + tid] =
                red[tid] + red[64 + tid] + red[128 + tid] + red[192 + tid];
    } else if (b < 4 * T + 4) {
        // ---- S bias vectors: one mat per block, 4-way c-split ----
        const int mat = b - 4 * T;
        const int branch = mat >> 1, which = mat & 1;
        const float* cb = branch ? cbr : cbe;
        const float* W = (branch ? Wchr : Wche) + which * FIN * GO;
        float acc = 0.f;
#pragma unroll
        for (int cj = 0; cj < 8; cj++) {
            int c = cc * 8 + cj;
            float s = 0.f;
#pragma unroll
            for (int t = 0; t < T; t++) s += W[(c * T + t) * GO + o];
            acc += cb[c] * s;
        }
        red[tid] = acc;
        __syncthreads();
        if (tid < 64)
            g_S[mat][tid] =
                red[tid] + red[64 + tid] + red[128 + tid] + red[192 + tid];
    } else {
        // ---- edges: weights, wsum, neighbor lists ----
        int t = tid;
        for (int g = 0; g < 2; g++) {
            const int* ei = g ? eir : eie;
            int E = g ? Er : Ee;
            int V = g ? VR : VE;
            if (t < E) {
                int s = ei[t], d = ei[E + t];
                int degs = 0, degd = 0;
                for (int i = 0; i < E; i++) {
                    int si = ei[i];
                    degs += (si == s);
                    degd += (si == d);
                }
                float ds = degs > 0 ? rsqrtf((float)degs) : 0.f;
                float dd = degd > 0 ? rsqrtf((float)degd) : 0.f;
                g_we[g][t] = -ds * dd;
            }
            __syncthreads();
            if (t < 16) {
                float ws = 0.f;
                int cnt = 0;
                if (t < V) {
                    for (int e = 0; e < E; e++) {
                        if (ei[E + e] == t) ws += g_we[g][e];
                        if (ei[e] == t && cnt < 8) {
                            g_nbrd[g][t][cnt] = ei[E + e];
                            g_nbrw[g][t][cnt] = g_we[g][e];
                            cnt++;
                        }
                    }
                }
                g_wsum[g][t] = ws;
                g_ncnt[g][t] = cnt;
            }
            __syncthreads();
        }
    }
}

// ---------------- precompute: A matrices (tiled) + C vectors, one kernel ------
__global__ void __launch_bounds__(256) k_AC(
    const float* __restrict__ Pe, const float* __restrict__ Pr,
    const float* __restrict__ pbe, const float* __restrict__ pbr,
    const float* __restrict__ chbe, const float* __restrict__ chbr) {
    __shared__ float sP[64 * 64];
    __shared__ float sQ[64 * 64];
    __shared__ float sU0[T * GO];
    __shared__ float sU1[T * GO];
    const int tid = threadIdx.x;
    const int b = blockIdx.x;

    if (b < (VE + VR) * 4) {
        // ---- A block: node v, h-chunk hb..hb+63 ----
        const int vb = b >> 2, hb = (b & 3) * 64;
        const int br = vb >= VE;
        const int v = br ? vb - VE : vb;
        const float* P = br ? Pr : Pe;
        float* A = br ? g_A_err : g_A_ecc;

        {
            const float4* U0 = (const float4*)g_U[2 * br];
            const float4* U1 = (const float4*)g_U[2 * br + 1];
            float4* s0 = (float4*)sU0;
            float4* s1 = (float4*)sU1;
            for (int i = tid; i < T * GO / 4; i += 256) {
                s0[i] = U0[i];
                s1[i] = U1[i];
            }
        }
        const int cnt = g_ncnt[br][v];
        int nd[4];
        float nw[4];
#pragma unroll
        for (int j = 0; j < 4; j++) {
            nd[j] = (j < cnt) ? g_nbrd[br][v][j] : 0;
            nw[j] = (j < cnt) ? g_nbrw[br][v][j] : 0.f;
        }
        for (int i4 = tid; i4 < 1024; i4 += 256) {
            int oo = i4 >> 4, hl4 = (i4 & 15) * 4;
            const float4* pv =
                (const float4*)&P[(v * GO + oo) * H + hb + hl4];
            ((float4*)sP)[i4] = *pv;
            float4 q = make_float4(0.f, 0.f, 0.f, 0.f);
#pragma unroll
            for (int j = 0; j < 4; j++) {
                if (j < cnt) {
                    float4 pd = *(const float4*)&P[(nd[j] * GO + oo) * H + hb + hl4];
                    q.x += nw[j] * pd.x;
                    q.y += nw[j] * pd.y;
                    q.z += nw[j] * pd.z;
                    q.w += nw[j] * pd.w;
                }
            }
            ((float4*)sQ)[i4] = q;
        }
        __syncthreads();

        const int hl4 = (tid & 15) * 4;
        const int tpg = tid >> 4;
        for (int tp = tpg; tp < T; tp += 16) {
            float4 acc = make_float4(0.f, 0.f, 0.f, 0.f);
#pragma unroll 16
            for (int o = 0; o < 64; o++) {
                float4 p = *(const float4*)&sP[o * 64 + hl4];
                float4 q = *(const float4*)&sQ[o * 64 + hl4];
                float u0 = sU0[tp * GO + o];
                float u1 = sU1[tp * GO + o];
                acc.x += u0 * p.x + u1 * q.x;
                acc.y += u0 * p.y + u1 * q.y;
                acc.z += u0 * p.z + u1 * q.z;
                acc.w += u0 * p.w + u1 * q.w;
            }
            *(float4*)&A[(v * T + tp) * H + hb + hl4] = acc;
        }
    } else {
        // ---- C block: branch br, 32 h-columns ----
        const int cb = b - (VE + VR) * 4;   // 0..15
        const int br = cb >> 3;
        const int hc = cb & 7;
        const float* chb = br ? chbr : chbe;
        const float* pb = br ? pbr : pbe;
        const float* P = br ? Pr : Pe;
        const int V = br ? VR : VE;
        float* cfo = sP;          // 64: chb + S0
        float* s1v = sP + 64;     // 64: S1
        float* ws = sP + 128;     // 16: wsum
        float* red = sP + 160;    // 256: partials

        if (tid < 64) {
            cfo[tid] = chb[tid] + g_S[2 * br][tid];
            s1v[tid] = g_S[2 * br + 1][tid];
        }
        if (tid < 16) ws[tid] = g_wsum[br][tid];
        __syncthreads();

        const int lane = tid & 31, rp = tid >> 5;
        const int h = hc * 32 + lane;
        const int R = V * GO;
        const int RP = R >> 3;
        float acc = 0.f;
#pragma unroll 4
        for (int r = rp * RP; r < (rp + 1) * RP; r++) {
            int o = r & 63, v = r >> 6;
            float coef = cfo[o] + s1v[o] * ws[v];
            acc += coef * P[r * H + h];
        }
        red[tid] = acc;
        __syncthreads();
        if (tid < 32) {
            float s = pb[h];
#pragma unroll
            for (int j = 0; j < 8; j++) s += red[j * 32 + lane];
            g_C[br][h] = s;
        }
    }
}

// ---------------- main fused kernel: 2 GEMMs + gated tail ----------------
extern __shared__ float sm[];

// one GEMM phase with 4-deep A prefetch pipeline
#define GEMM_PHASE(Aarr, Xs, K, Cbr, DST)                                      \
    {                                                                          \
        unsigned long long acc[8][2];                                          \
        _Pragma("unroll") for (int i = 0; i < 8; i++) {                        \
            acc[i][0] = 0ull;                                                  \
            acc[i][1] = 0ull;                                                  \
        }                                                                      \
        const ulonglong2* A4 = (const ulonglong2*)(Aarr);                      \
        ulonglong2 abuf[PFD];                                                  \
        _Pragma("unroll") for (int j = 0; j < PFD; j++)                        \
            abuf[j] = A4[j * 64 + n_id];                                       \
        _Pragma("unroll 4") for (int k = 0; k < (K); k++) {                    \
            ulonglong2 a = abuf[k & (PFD - 1)];                                \
            abuf[k & (PFD - 1)] = A4[(k + PFD) * 64 + n_id];                   \
            const float* xp = (Xs) + k * XSE + m_id * 8;                       \
            float4 x0 = *(const float4*)xp;                                    \
            float4 x1 = *(const float4*)(xp + 4);                              \
            unsigned long long xd;                                             \
            xd = pack2(x0.x);                                                  \
            acc[0][0] = fma2(xd, a.x, acc[0][0]);                              \
            acc[0][1] = fma2(xd, a.y, acc[0][1]);                              \
            xd = pack2(x0.y);                                                  \
            acc[1][0] = fma2(xd, a.x, acc[1][0]);                              \
            acc[1][1] = fma2(xd, a.y, acc[1][1]);                              \
            xd = pack2(x0.z);                                                  \
            acc[2][0] = fma2(xd, a.x, acc[2][0]);                              \
            acc[2][1] = fma2(xd, a.y, acc[2][1]);                              \
            xd = pack2(x0.w);                                                  \
            acc[3][0] = fma2(xd, a.x, acc[3][0]);                              \
            acc[3][1] = fma2(xd, a.y, acc[3][1]);                              \
            xd = pack2(x1.x);                                                  \
            acc[4][0] = fma2(xd, a.x, acc[4][0]);                              \
            acc[4][1] = fma2(xd, a.y, acc[4][1]);                              \
            xd = pack2(x1.y);                                                  \
            acc[5][0] = fma2(xd, a.x, acc[5][0]);                              \
            acc[5][1] = fma2(xd, a.y, acc[5][1]);                              \
            xd = pack2(x1.z);                                                  \
            acc[6][0] = fma2(xd, a.x, acc[6][0]);                              \
            acc[6][1] = fma2(xd, a.y, acc[6][1]);                              \
            xd = pack2(x1.w);                                                  \
            acc[7][0] = fma2(xd, a.x, acc[7][0]);                              \
            acc[7][1] = fma2(xd, a.y, acc[7][1]);                              \
        }                                                                      \
        float4 Cv = *(const float4*)&g_C[Cbr][n_id * 4];                       \
        _Pragma("unroll") for (int i = 0; i < 8; i++) {                        \
            int r = m_id * 8 + i;                                              \
            float2 lo = unpack2(acc[i][0]);                                    \
            float2 hi = unpack2(acc[i][1]);                                    \
            *(float4*)&(DST)[r * H + n_id * 4] =                               \
                make_float4(lo.x + Cv.x, lo.y + Cv.y, hi.x + Cv.z,             \
                            hi.y + Cv.w);                                      \
        }                                                                      \
    }

__global__ void __launch_bounds__(256)
k_main(const float* __restrict__ ecc, const float* __restrict__ err,
       const float* __restrict__ attnW, const float* __restrict__ attnb,
       const float* __restrict__ fc2W, const float* __restrict__ fc2b,
       float* __restrict__ out) {
    float* Xe = sm;                    // [KE][XSE] transposed X_ecc tile
    float* Xr = Xe + KE * XSE;         // [KR][XSE]
    float* eg = Xr + KR * XSE;         // [TB][H]
    float* rg = eg + TB * H;           // [TB][H]

    const int tid = threadIdx.x;
    const int rb = blockIdx.x * TB;

    for (int i = tid; i < TB * KE; i += 256) {
        int r = i / KE, k = i - r * KE;
        Xe[k * XSE + r] = ecc[(rb + r) * KE + k];
    }
    for (int i = tid; i < TB * KR; i += 256) {
        int r = i / KR, k = i - r * KR;
        Xr[k * XSE + r] = err[(rb + r) * KR + k];
    }
    __syncthreads();

    const int n_id = tid & 63;   // 64 column groups of 4
    const int m_id = tid >> 6;   // 4 row groups of 8

    GEMM_PHASE(g_A_ecc, Xe, KE, 0, eg)
    GEMM_PHASE(g_A_err, Xr, KR, 1, rg)
    __syncthreads();

    // -------- tail: gated fusion, 1 warp per 4 rows --------
    const int lane = tid & 31;
    const int w = tid >> 5;
    const float attnb_v = attnb[0];
    const float fc2b_v = fc2b[0];
    for (int r = w * 4; r < w * 4 + 4; r++) {
        const float* egr = eg + r * H;
        const float* rgr = rg + r * H;
        float p = 0.f;
#pragma unroll
        for (int j = lane; j < H; j += 32)
            p += tanhf(egr[j] + rgr[j]) * attnW[j];
#pragma unroll
        for (int o = 16; o; o >>= 1) p += __shfl_xor_sync(0xffffffffu, p, o);
        float attn = 1.f / (1.f + expf(-(p + attnb_v)));
        float q = 0.f;
#pragma unroll
        for (int j = lane; j < H; j += 32) {
            float f = attn * egr[j] + (1.f - attn) * rgr[j];
            q += fmaxf(f, 0.f) * fc2W[j];
        }
#pragma unroll
        for (int o = 16; o; o >>= 1) q += __shfl_xor_sync(0xffffffffu, q, o);
        if (lane == 0) out[rb + r] = 1.f / (1.f + expf(-(q + fc2b_v)));
    }
}

// ---------------- launch ----------------
extern "C" void kernel_launch(void* const* d_in, const int* in_sizes, int n_in,
                              void* d_out, int out_size) {
    const float* ecc = (const float*)d_in[0];
    const float* err = (const float*)d_in[1];
    const float* conv_ecc_w = (const float*)d_in[2];
    const float* conv_ecc_b = (const float*)d_in[3];
    const float* conv_err_w = (const float*)d_in[4];
    const float* conv_err_b = (const float*)d_in[5];
    const float* cheb_ecc_W = (const float*)d_in[6];
    const float* cheb_ecc_b = (const float*)d_in[7];
    const float* cheb_err_W = (const float*)d_in[8];
    const float* cheb_err_b = (const float*)d_in[9];
    const float* ecc_proj_W = (const float*)d_in[10];
    const float* ecc_proj_b = (const float*)d_in[11];
    const float* err_proj_W = (const float*)d_in[12];
    const float* err_proj_b = (const float*)d_in[13];
    const float* attn_W = (const float*)d_in[14];
    const float* attn_b = (const float*)d_in[15];
    const float* fc2_W = (const float*)d_in[16];
    const float* fc2_b = (const float*)d_in[17];
    const int* ei_ecc = (const int*)d_in[18];
    const int* ei_err = (const int*)d_in[19];
    const int Ee = in_sizes[18] / 2;
    const int Er = in_sizes[19] / 2;

    k_prep<<<4 * T + 5, 256>>>(conv_ecc_w, conv_ecc_b, conv_err_w, conv_err_b,
                               cheb_ecc_W, cheb_err_W, ei_ecc, Ee, ei_err, Er);
    k_AC<<<(VE + VR) * 4 + 16, 256>>>(ecc_proj_W, err_proj_W,
                                      ecc_proj_b, err_proj_b,
                                      cheb_ecc_b, cheb_err_b);

    const size_t smem = (size_t)(KE * XSE + KR * XSE + 2 * TB * H) * sizeof(float);
    cudaFuncSetAttribute(k_main, cudaFuncAttributeMaxDynamicSharedMemorySize,
                         (int)smem);
    k_main<<<BATCH / TB, 256, smem>>>(ecc, err, attn_W, attn_b, fc2_W, fc2_b,
                                      (float*)d_out);
}

// round 6
// speedup vs baseline: 3.8183x; 1.7994x over previous
#include <cuda_runtime.h>
#include <cuda_bf16.h>
#include <math.h>
#include <stdint.h>

#define BATCH 4096
#define T 25
#define CT 32
#define FIN 800
#define GO 64
#define H 256
#define VE 16
#define VR 12
#define KE 400
#define KR 300
#define KPE 448           /* padded K, ecc (7 chunks of 64) */
#define KPR 320           /* padded K, err (5 chunks of 64) */
#define NCHE 7
#define NCHR 5
#define KC 64             /* k per staged chunk */
#define MT 32             /* batch rows per CTA */
#define RSB 144           /* staged tile row stride, bytes (36 words: 16B-aligned + conflict-free) */
#define ES 260            /* eg/rg row stride, floats */
#define B_ERR_OFS (256 * KPE)
#define B_TOT (256 * KPE + 256 * KPR)

// ---------------- device scratch ----------------
__device__ float g_U[4][T * GO];
__device__ float g_S[4][GO];
__device__ float g_we[2][64];
__device__ float g_wsum[2][16];
__device__ int   g_nbrd[2][16][8];
__device__ float g_nbrw[2][16][8];
__device__ int   g_ncnt[2][16];
__device__ __align__(16) __nv_bfloat16 g_Bh[B_TOT];   // [n][K_pad], ecc then err
__device__ __align__(16) __nv_bfloat16 g_Bl[B_TOT];
__device__ float g_C[2][H];

// ---------------- mma.sync m16n8k16 bf16 (row.col, f32 acc) ----------------
__device__ __forceinline__ void mma16816(float* d, uint32_t a0, uint32_t a1,
                                         uint32_t a2, uint32_t a3,
                                         uint32_t b0, uint32_t b1) {
    asm volatile(
        "mma.sync.aligned.m16n8k16.row.col.f32.bf16.bf16.f32 "
        "{%0,%1,%2,%3}, {%4,%5,%6,%7}, {%8,%9}, {%0,%1,%2,%3};"
        : "+f"(d[0]), "+f"(d[1]), "+f"(d[2]), "+f"(d[3])
        : "r"(a0), "r"(a1), "r"(a2), "r"(a3), "r"(b0), "r"(b1));
}

__device__ __forceinline__ uint32_t pack_bf2(__nv_bfloat16 lo, __nv_bfloat16 hi) {
    return ((uint32_t)__bfloat16_as_ushort(hi) << 16) |
           (uint32_t)__bfloat16_as_ushort(lo);
}

// ---------------- precompute: U, S, edges, nbr lists ------------
__global__ void __launch_bounds__(256) k_prep(
    const float* __restrict__ cwe, const float* __restrict__ cbe,
    const float* __restrict__ cwr, const float* __restrict__ cbr,
    const float* __restrict__ Wche, const float* __restrict__ Wchr,
    const int* __restrict__ eie, int Ee, const int* __restrict__ eir, int Er) {
    __shared__ float red[256];
    const int b = blockIdx.x;
    const int tid = threadIdx.x;
    const int o = tid & 63;
    const int cc = tid >> 6;

    if (b < 4 * T) {
        const int mat = b / T, tp = b % T;
        const int branch = mat >> 1, which = mat & 1;
        const float* cw = branch ? cwr : cwe;
        const float* W = (branch ? Wchr : Wche) + which * FIN * GO;
        float acc = 0.f;
#pragma unroll
        for (int k = 0; k < 3; k++) {
            int t = tp - k + 1;
            if (t >= 0 && t < T) {
#pragma unroll
                for (int cj = 0; cj < 8; cj++) {
                    int c = cc * 8 + cj;
                    acc += cw[c * 3 + k] * W[(c * T + t) * GO + o];
                }
            }
        }
        red[tid] = acc;
        __syncthreads();
        if (tid < 64)
            g_U[mat][tp * GO + tid] =
                red[tid] + red[64 + tid] + red[128 + tid] + red[192 + tid];
    } else if (b < 4 * T + 4) {
        const int mat = b - 4 * T;
        const int branch = mat >> 1, which = mat & 1;
        const float* cb = branch ? cbr : cbe;
        const float* W = (branch ? Wchr : Wche) + which * FIN * GO;
        float acc = 0.f;
#pragma unroll
        for (int cj = 0; cj < 8; cj++) {
            int c = cc * 8 + cj;
            float s = 0.f;
#pragma unroll
            for (int t = 0; t < T; t++) s += W[(c * T + t) * GO + o];
            acc += cb[c] * s;
        }
        red[tid] = acc;
        __syncthreads();
        if (tid < 64)
            g_S[mat][tid] =
                red[tid] + red[64 + tid] + red[128 + tid] + red[192 + tid];
    } else {
        int t = tid;
        for (int g = 0; g < 2; g++) {
            const int* ei = g ? eir : eie;
            int E = g ? Er : Ee;
            int V = g ? VR : VE;
            if (t < E) {
                int s = ei[t], d = ei[E + t];
                int degs = 0, degd = 0;
                for (int i = 0; i < E; i++) {
                    int si = ei[i];
                    degs += (si == s);
                    degd += (si == d);
                }
                float ds = degs > 0 ? rsqrtf((float)degs) : 0.f;
                float dd = degd > 0 ? rsqrtf((float)degd) : 0.f;
                g_we[g][t] = -ds * dd;
            }
            __syncthreads();
            if (t < 16) {
                float ws = 0.f;
                int cnt = 0;
                if (t < V) {
                    for (int e = 0; e < E; e++) {
                        if (ei[E + e] == t) ws += g_we[g][e];
                        if (ei[e] == t && cnt < 8) {
                            g_nbrd[g][t][cnt] = ei[E + e];
                            g_nbrw[g][t][cnt] = g_we[g][e];
                            cnt++;
                        }
                    }
                }
                g_wsum[g][t] = ws;
                g_ncnt[g][t] = cnt;
            }
            __syncthreads();
        }
    }
}

// ------- precompute: B = collapsed weights as bf16 hi/lo [n][K_pad], + C -------
__global__ void __launch_bounds__(256) k_AC(
    const float* __restrict__ Pe, const float* __restrict__ Pr,
    const float* __restrict__ pbe, const float* __restrict__ pbr,
    const float* __restrict__ chbe, const float* __restrict__ chbr) {
    __shared__ float sP[64 * 64];
    __shared__ float sQ[64 * 64];
    __shared__ float sU0[T * GO];
    __shared__ float sU1[T * GO];
    const int tid = threadIdx.x;
    const int b = blockIdx.x;

    if (b < (VE + VR) * 4) {
        // ---- A block: node v, h-chunk hb..hb+63 ----
        const int vb = b >> 2, hb = (b & 3) * 64;
        const int br = vb >= VE;
        const int v = br ? vb - VE : vb;
        const float* P = br ? Pr : Pe;
        const size_t base = br ? (size_t)B_ERR_OFS : 0;
        const int KP = br ? KPR : KPE;

        {
            const float4* U0 = (const float4*)g_U[2 * br];
            const float4* U1 = (const float4*)g_U[2 * br + 1];
            float4* s0 = (float4*)sU0;
            float4* s1 = (float4*)sU1;
            for (int i = tid; i < T * GO / 4; i += 256) {
                s0[i] = U0[i];
                s1[i] = U1[i];
            }
        }
        const int cnt = g_ncnt[br][v];
        int nd[4];
        float nw[4];
#pragma unroll
        for (int j = 0; j < 4; j++) {
            nd[j] = (j < cnt) ? g_nbrd[br][v][j] : 0;
            nw[j] = (j < cnt) ? g_nbrw[br][v][j] : 0.f;
        }
        for (int i4 = tid; i4 < 1024; i4 += 256) {
            int oo = i4 >> 4, hl4 = (i4 & 15) * 4;
            ((float4*)sP)[i4] = *(const float4*)&P[(v * GO + oo) * H + hb + hl4];
            float4 q = make_float4(0.f, 0.f, 0.f, 0.f);
#pragma unroll
            for (int j = 0; j < 4; j++) {
                if (j < cnt) {
                    float4 pd = *(const float4*)&P[(nd[j] * GO + oo) * H + hb + hl4];
                    q.x += nw[j] * pd.x;
                    q.y += nw[j] * pd.y;
                    q.z += nw[j] * pd.z;
                    q.w += nw[j] * pd.w;
                }
            }
            ((float4*)sQ)[i4] = q;
        }
        __syncthreads();

        const int hl4 = (tid & 15) * 4;
        const int tpg = tid >> 4;
        for (int tp = tpg; tp < T; tp += 16) {
            float4 acc = make_float4(0.f, 0.f, 0.f, 0.f);
#pragma unroll 16
            for (int o = 0; o < 64; o++) {
                float4 p = *(const float4*)&sP[o * 64 + hl4];
                float4 q = *(const float4*)&sQ[o * 64 + hl4];
                float u0 = sU0[tp * GO + o];
                float u1 = sU1[tp * GO + o];
                acc.x += u0 * p.x + u1 * q.x;
                acc.y += u0 * p.y + u1 * q.y;
                acc.z += u0 * p.z + u1 * q.z;
                acc.w += u0 * p.w + u1 * q.w;
            }
            const int kg = v * T + tp;
            float vals[4] = {acc.x, acc.y, acc.z, acc.w};
#pragma unroll
            for (int j = 0; j < 4; j++) {
                int n = hb + hl4 + j;
                __nv_bfloat16 hi = __float2bfloat16(vals[j]);
                __nv_bfloat16 lo =
                    __float2bfloat16(vals[j] - __bfloat162float(hi));
                size_t idx = base + (size_t)n * KP + kg;
                g_Bh[idx] = hi;
                g_Bl[idx] = lo;
            }
        }
    } else if (b == (VE + VR) * 4 + 16) {
        // ---- zero-fill K padding: ecc k in [400,448), err k in [300,320) ----
        const int NE = 256 * (KPE - KE);   // 256*48
        const int NR = 256 * (KPR - KR);   // 256*20
        __nv_bfloat16 z = __float2bfloat16(0.f);
        for (int i = tid; i < NE + NR; i += 256) {
            size_t idx;
            if (i < NE) {
                int n = i / (KPE - KE), k = KE + i % (KPE - KE);
                idx = (size_t)n * KPE + k;
            } else {
                int r = i - NE;
                int n = r / (KPR - KR), k = KR + r % (KPR - KR);
                idx = (size_t)B_ERR_OFS + (size_t)n * KPR + k;
            }
            g_Bh[idx] = z;
            g_Bl[idx] = z;
        }
    } else {
        // ---- C block: branch br, 32 h-columns ----
        const int cb = b - (VE + VR) * 4;   // 0..15
        const int br = cb >> 3;
        const int hc = cb & 7;
        const float* chb = br ? chbr : chbe;
        const float* pb = br ? pbr : pbe;
        const float* P = br ? Pr : Pe;
        const int V = br ? VR : VE;
        float* cfo = sP;
        float* s1v = sP + 64;
        float* ws = sP + 128;
        float* red = sP + 160;

        if (tid < 64) {
            cfo[tid] = chb[tid] + g_S[2 * br][tid];
            s1v[tid] = g_S[2 * br + 1][tid];
        }
        if (tid < 16) ws[tid] = g_wsum[br][tid];
        __syncthreads();

        const int lane = tid & 31, rp = tid >> 5;
        const int h = hc * 32 + lane;
        const int R = V * GO;
        const int RP = R >> 3;
        float acc = 0.f;
#pragma unroll 4
        for (int r = rp * RP; r < (rp + 1) * RP; r++) {
            int o = r & 63, v = r >> 6;
            float coef = cfo[o] + s1v[o] * ws[v];
            acc += coef * P[r * H + h];
        }
        red[tid] = acc;
        __syncthreads();
        if (tid < 32) {
            float s = pb[h];
#pragma unroll
            for (int j = 0; j < 8; j++) s += red[j * 32 + lane];
            g_C[br][h] = s;
        }
    }
}

// ---------------- main: HMMA bf16-split GEMM + gated tail ----------------
// smem layout (bytes):
//   sBh @ 0        : 256 * 144 = 36864
//   sBl @ 36864    : 36864
//   sXh @ 73728    : 32 * 144 = 4608
//   sXl @ 78336    : 4608
//   eg  @ 82944    : 32 * 260 * 4 = 33280
//   rg  @ 116224   : 33280
//   total 149504
#define SM_MAIN 149504

extern __shared__ char smx[];

__global__ void __launch_bounds__(256, 1)
k_main(const float* __restrict__ ecc, const float* __restrict__ err,
       const float* __restrict__ attnW, const float* __restrict__ attnb,
       const float* __restrict__ fc2W, const float* __restrict__ fc2b,
       float* __restrict__ out) {
    char* sBh = smx;
    char* sBl = smx + 36864;
    char* sXh = smx + 73728;
    char* sXl = smx + 78336;
    float* eg = (float*)(smx + 82944);
    float* rg = (float*)(smx + 116224);

    const int tid = threadIdx.x;
    const int wid = tid >> 5;
    const int lane = tid & 31;
    const int g = lane >> 2;        // fragment group row/col
    const int i2 = (lane & 3) * 2;  // fragment k pair base
    const int ns = wid * 32;        // this warp's n slice
    const int rb = blockIdx.x * MT;

    for (int br = 0; br < 2; br++) {
        const float* X = br ? err : ecc;
        const int Kreal = br ? KR : KE;
        const int nch = br ? NCHR : NCHE;
        const int KP = br ? KPR : KPE;
        const char* gBh = (const char*)(g_Bh + (br ? B_ERR_OFS : 0));
        const char* gBl = (const char*)(g_Bl + (br ? B_ERR_OFS : 0));

        float d[2][4][4];
#pragma unroll
        for (int mt = 0; mt < 2; mt++)
#pragma unroll
            for (int nt = 0; nt < 4; nt++)
#pragma unroll
                for (int j = 0; j < 4; j++) d[mt][nt][j] = 0.f;

        for (int c = 0; c < nch; c++) {
            __syncthreads();   // previous chunk's mma reads done
            // ---- stage X chunk: 32 rows x 64 k, fp32 -> bf16 hi/lo ----
#pragma unroll
            for (int it = 0; it < 2; it++) {
                int idx = tid + it * 256;
                int row = idx >> 4, kq = idx & 15;
                int k = c * KC + kq * 4;
                float4 x = make_float4(0.f, 0.f, 0.f, 0.f);
                if (k < Kreal)
                    x = *(const float4*)&X[(size_t)(rb + row) * Kreal + k];
                __nv_bfloat16 h0 = __float2bfloat16(x.x);
                __nv_bfloat16 h1 = __float2bfloat16(x.y);
                __nv_bfloat16 h2 = __float2bfloat16(x.z);
                __nv_bfloat16 h3 = __float2bfloat16(x.w);
                __nv_bfloat16 l0 = __float2bfloat16(x.x - __bfloat162float(h0));
                __nv_bfloat16 l1 = __float2bfloat16(x.y - __bfloat162float(h1));
                __nv_bfloat16 l2 = __float2bfloat16(x.z - __bfloat162float(h2));
                __nv_bfloat16 l3 = __float2bfloat16(x.w - __bfloat162float(h3));
                uint2 ph = make_uint2(pack_bf2(h0, h1), pack_bf2(h2, h3));
                uint2 pl = make_uint2(pack_bf2(l0, l1), pack_bf2(l2, l3));
                *(uint2*)(sXh + row * RSB + kq * 8) = ph;
                *(uint2*)(sXl + row * RSB + kq * 8) = pl;
            }
            // ---- stage B chunk: 256 n x 64 k bf16, 16B copies ----
#pragma unroll
            for (int it = 0; it < 8; it++) {
                int idx = tid + it * 256;
                int n = idx >> 3, q = idx & 7;
                size_t gb = (size_t)n * KP * 2 + (size_t)c * KC * 2 + q * 16;
                *(uint4*)(sBh + n * RSB + q * 16) = *(const uint4*)(gBh + gb);
                *(uint4*)(sBl + n * RSB + q * 16) = *(const uint4*)(gBl + gb);
            }
            __syncthreads();

            // ---- 4 k-steps of m16n8k16, split-3 bf16 ----
#pragma unroll
            for (int ks = 0; ks < 4; ks++) {
                const int kb = ks * 32 + i2 * 2;   // byte offset of k pair
                uint32_t ah[2][4], al[2][4];
#pragma unroll
                for (int mt = 0; mt < 2; mt++) {
                    const char* hp = sXh + (mt * 16 + g) * RSB + kb;
                    const char* lp = sXl + (mt * 16 + g) * RSB + kb;
                    ah[mt][0] = *(const uint32_t*)hp;
                    ah[mt][1] = *(const uint32_t*)(hp + 8 * RSB);
                    ah[mt][2] = *(const uint32_t*)(hp + 16);
                    ah[mt][3] = *(const uint32_t*)(hp + 8 * RSB + 16);
                    al[mt][0] = *(const uint32_t*)lp;
                    al[mt][1] = *(const uint32_t*)(lp + 8 * RSB);
                    al[mt][2] = *(const uint32_t*)(lp + 16);
                    al[mt][3] = *(const uint32_t*)(lp + 8 * RSB + 16);
                }
#pragma unroll
                for (int nt = 0; nt < 4; nt++) {
                    const char* bh = sBh + (ns + nt * 8 + g) * RSB + kb;
                    const char* bl = sBl + (ns + nt * 8 + g) * RSB + kb;
                    uint32_t bh0 = *(const uint32_t*)bh;
                    uint32_t bh1 = *(const uint32_t*)(bh + 16);
                    uint32_t bl0 = *(const uint32_t*)bl;
                    uint32_t bl1 = *(const uint32_t*)(bl + 16);
#pragma unroll
                    for (int mt = 0; mt < 2; mt++) {
                        mma16816(d[mt][nt], ah[mt][0], ah[mt][1], ah[mt][2],
                                 ah[mt][3], bh0, bh1);
                        mma16816(d[mt][nt], ah[mt][0], ah[mt][1], ah[mt][2],
                                 ah[mt][3], bl0, bl1);
                        mma16816(d[mt][nt], al[mt][0], al[mt][1], al[mt][2],
                                 al[mt][3], bh0, bh1);
                    }
                }
            }
        }
        // ---- epilogue: fragments -> eg/rg smem ----
        float* G = br ? rg : eg;
#pragma unroll
        for (int mt = 0; mt < 2; mt++)
#pragma unroll
            for (int nt = 0; nt < 4; nt++) {
                int row = mt * 16 + g;
                int col = ns + nt * 8 + i2;
                G[row * ES + col] = d[mt][nt][0];
                G[row * ES + col + 1] = d[mt][nt][1];
                G[(row + 8) * ES + col] = d[mt][nt][2];
                G[(row + 8) * ES + col + 1] = d[mt][nt][3];
            }
    }
    __syncthreads();

    // -------- gated tail: 1 warp per 4 rows --------
    const float attnb_v = attnb[0];
    const float fc2b_v = fc2b[0];
    for (int r = wid * 4; r < wid * 4 + 4; r++) {
        const float* egr = eg + r * ES;
        const float* rgr = rg + r * ES;
        float p = 0.f;
#pragma unroll
        for (int j = lane; j < H; j += 32) {
            float ev = egr[j] + g_C[0][j];
            float rv = rgr[j] + g_C[1][j];
            p += tanhf(ev + rv) * attnW[j];
        }
#pragma unroll
        for (int o = 16; o; o >>= 1) p += __shfl_xor_sync(0xffffffffu, p, o);
        float attn = 1.f / (1.f + expf(-(p + attnb_v)));
        float q = 0.f;
#pragma unroll
        for (int j = lane; j < H; j += 32) {
            float ev = egr[j] + g_C[0][j];
            float rv = rgr[j] + g_C[1][j];
            float f = attn * ev + (1.f - attn) * rv;
            q += fmaxf(f, 0.f) * fc2W[j];
        }
#pragma unroll
        for (int o = 16; o; o >>= 1) q += __shfl_xor_sync(0xffffffffu, q, o);
        if (lane == 0) out[rb + r] = 1.f / (1.f + expf(-(q + fc2b_v)));
    }
}

// ---------------- launch ----------------
extern "C" void kernel_launch(void* const* d_in, const int* in_sizes, int n_in,
                              void* d_out, int out_size) {
    const float* ecc = (const float*)d_in[0];
    const float* err = (const float*)d_in[1];
    const float* conv_ecc_w = (const float*)d_in[2];
    const float* conv_ecc_b = (const float*)d_in[3];
    const float* conv_err_w = (const float*)d_in[4];
    const float* conv_err_b = (const float*)d_in[5];
    const float* cheb_ecc_W = (const float*)d_in[6];
    const float* cheb_ecc_b = (const float*)d_in[7];
    const float* cheb_err_W = (const float*)d_in[8];
    const float* cheb_err_b = (const float*)d_in[9];
    const float* ecc_proj_W = (const float*)d_in[10];
    const float* ecc_proj_b = (const float*)d_in[11];
    const float* err_proj_W = (const float*)d_in[12];
    const float* err_proj_b = (const float*)d_in[13];
    const float* attn_W = (const float*)d_in[14];
    const float* attn_b = (const float*)d_in[15];
    const float* fc2_W = (const float*)d_in[16];
    const float* fc2_b = (const float*)d_in[17];
    const int* ei_ecc = (const int*)d_in[18];
    const int* ei_err = (const int*)d_in[19];
    const int Ee = in_sizes[18] / 2;
    const int Er = in_sizes[19] / 2;

    k_prep<<<4 * T + 5, 256>>>(conv_ecc_w, conv_ecc_b, conv_err_w, conv_err_b,
                               cheb_ecc_W, cheb_err_W, ei_ecc, Ee, ei_err, Er);
    k_AC<<<(VE + VR) * 4 + 17, 256>>>(ecc_proj_W, err_proj_W,
                                      ecc_proj_b, err_proj_b,
                                      cheb_ecc_b, cheb_err_b);

    cudaFuncSetAttribute(k_main, cudaFuncAttributeMaxDynamicSharedMemorySize,
                         SM_MAIN);
    k_main<<<BATCH / MT, 256, SM_MAIN>>>(ecc, err, attn_W, attn_b,
                                         fc2_W, fc2_b, (float*)d_out);
}